// round 16
// baseline (speedup 1.0000x reference)
#include <cuda_runtime.h>
#include <cuda_fp16.h>

// out[e] = sigmoid( dot( x[src[e], 0:128], x[dst[e], 128:256] ) )
// x: [N_NODES, 256] fp32. edge_label_index: [2, N_EDGES] int32.
//
// Pipeline (all per launch, graph-capturable):
//  Z: zero histogram
//  H: histogram of src >> 8 (256-node buckets, smem-accumulated)
//  S: exclusive scan -> bucketStart, scatterOffset (1 block)
//  C: ticket-scatter (src,dst) + e into bucket-sorted order
//  convert: x fp32 -> fp16 table (51.2 MB), streaming L2 hints
//  D: gather over sorted edges. Each bucket's 64 KB src window is
//     L1-resident (src via __ldg); dst + sorted records via __ldcs so the
//     stream doesn't evict the src window. 8 edges/warp, f32x2 dot,
//     merging butterfly.

#define MAX_EDGES 1000000
#define MAX_BUCK  512
#define HIDDEN    256
#define HALF      128
#define EPW       8
#define BSHIFT    8      // 256 nodes per bucket
#define BPB       3      // blocks per bucket

__device__ static __half g_xh[(size_t)131072 * HIDDEN];  // fp16 table (padded)
__device__ static int2   g_sd[MAX_EDGES];                // sorted (src,dst)
__device__ static int    g_se[MAX_EDGES];                // sorted edge id
__device__ static int    g_hist[MAX_BUCK];
__device__ static int    g_start[MAX_BUCK + 1];
__device__ static int    g_off[MAX_BUCK];

__device__ __forceinline__ float sigmoidf(float v)
{
    return __fdividef(1.0f, 1.0f + __expf(-v));
}

// ---------------- Z: zero histogram ----------------
__global__ void zero_kernel()
{
    int t = threadIdx.x;
    if (t < MAX_BUCK) g_hist[t] = 0;
}

// ---------------- H: histogram of src buckets ----------------
__global__ __launch_bounds__(256)
void hist_kernel(const int* __restrict__ eidx, int n_edges)
{
    __shared__ int sh[MAX_BUCK];
    for (int t = threadIdx.x; t < MAX_BUCK; t += blockDim.x) sh[t] = 0;
    __syncthreads();
    for (int e = blockIdx.x * blockDim.x + threadIdx.x; e < n_edges;
         e += gridDim.x * blockDim.x)
        atomicAdd(&sh[__ldcs(&eidx[e]) >> BSHIFT], 1);
    __syncthreads();
    for (int t = threadIdx.x; t < MAX_BUCK; t += blockDim.x)
        if (sh[t]) atomicAdd(&g_hist[t], sh[t]);
}

// ---------------- S: exclusive scan (1 block, 512 threads) ----------------
__global__ void scan_kernel()
{
    __shared__ int sh[MAX_BUCK];
    int t = threadIdx.x;
    int v = g_hist[t];
    sh[t] = v;
    __syncthreads();
    // Hillis-Steele inclusive scan
    for (int d = 1; d < MAX_BUCK; d <<= 1) {
        int add = (t >= d) ? sh[t - d] : 0;
        __syncthreads();
        sh[t] += add;
        __syncthreads();
    }
    int incl = sh[t];
    g_start[t + 1] = incl;
    g_off[t]       = incl - v;   // exclusive
    if (t == 0) g_start[0] = 0;
}

// ---------------- C: ticket scatter ----------------
__global__ __launch_bounds__(256)
void scatter_kernel(const int* __restrict__ eidx, int n_edges)
{
    for (int e = blockIdx.x * blockDim.x + threadIdx.x; e < n_edges;
         e += gridDim.x * blockDim.x) {
        int s = __ldcs(&eidx[e]);
        int d = __ldcs(&eidx[n_edges + e]);
        int pos = atomicAdd(&g_off[s >> BSHIFT], 1);
        g_sd[pos] = make_int2(s, d);
        g_se[pos] = e;
    }
}

// ---------------- convert: fp32 -> fp16 table ----------------
__device__ __forceinline__ unsigned long long pol_evict_first()
{
    unsigned long long p;
    asm("createpolicy.fractional.L2::evict_first.b64 %0, 1.0;" : "=l"(p));
    return p;
}
__device__ __forceinline__ unsigned long long pol_evict_last()
{
    unsigned long long p;
    asm("createpolicy.fractional.L2::evict_last.b64 %0, 1.0;" : "=l"(p));
    return p;
}

__global__ __launch_bounds__(256)
void convert_kernel(const float* __restrict__ x, int n8)
{
    int i = blockIdx.x * blockDim.x + threadIdx.x;
    if (i >= n8) return;

    unsigned long long pf = pol_evict_first();
    unsigned long long pl = pol_evict_last();

    const float4* src = reinterpret_cast<const float4*>(x) + 2 * i;
    float4 v0, v1;
    asm("ld.global.nc.L2::cache_hint.v4.f32 {%0,%1,%2,%3}, [%4], %5;"
        : "=f"(v0.x), "=f"(v0.y), "=f"(v0.z), "=f"(v0.w) : "l"(src), "l"(pf));
    asm("ld.global.nc.L2::cache_hint.v4.f32 {%0,%1,%2,%3}, [%4], %5;"
        : "=f"(v1.x), "=f"(v1.y), "=f"(v1.z), "=f"(v1.w) : "l"(src + 1), "l"(pf));

    __half2 h0 = __floats2half2_rn(v0.x, v0.y);
    __half2 h1 = __floats2half2_rn(v0.z, v0.w);
    __half2 h2 = __floats2half2_rn(v1.x, v1.y);
    __half2 h3 = __floats2half2_rn(v1.z, v1.w);
    unsigned u0 = *reinterpret_cast<unsigned*>(&h0);
    unsigned u1 = *reinterpret_cast<unsigned*>(&h1);
    unsigned u2 = *reinterpret_cast<unsigned*>(&h2);
    unsigned u3 = *reinterpret_cast<unsigned*>(&h3);

    uint4* dst = reinterpret_cast<uint4*>(g_xh) + i;
    asm volatile("st.global.L2::cache_hint.v4.b32 [%0], {%1,%2,%3,%4}, %5;"
                 :: "l"(dst), "r"(u0), "r"(u1), "r"(u2), "r"(u3), "l"(pl)
                 : "memory");
}

// f32x2 dot of 4 halves (fp32 accumulation) — R13-measured best.
__device__ __forceinline__ float dot4h(uint2 ua, uint2 ub)
{
    __half2 a0 = *reinterpret_cast<__half2*>(&ua.x);
    __half2 a1 = *reinterpret_cast<__half2*>(&ua.y);
    __half2 b0 = *reinterpret_cast<__half2*>(&ub.x);
    __half2 b1 = *reinterpret_cast<__half2*>(&ub.y);
    float2 fa0 = __half22float2(a0), fa1 = __half22float2(a1);
    float2 fb0 = __half22float2(b0), fb1 = __half22float2(b1);
    unsigned long long A0, B0, A1, B1, ACC;
    asm("mov.b64 %0, {%1, %2};" : "=l"(A0) : "f"(fa0.x), "f"(fa0.y));
    asm("mov.b64 %0, {%1, %2};" : "=l"(B0) : "f"(fb0.x), "f"(fb0.y));
    asm("mov.b64 %0, {%1, %2};" : "=l"(A1) : "f"(fa1.x), "f"(fa1.y));
    asm("mov.b64 %0, {%1, %2};" : "=l"(B1) : "f"(fb1.x), "f"(fb1.y));
    asm("mul.rn.f32x2 %0, %1, %2;" : "=l"(ACC) : "l"(A0), "l"(B0));
    asm("fma.rn.f32x2 %0, %1, %2, %3;" : "=l"(ACC) : "l"(A1), "l"(B1), "l"(ACC));
    float lo, hi;
    asm("mov.b64 {%0, %1}, %2;" : "=f"(lo), "=f"(hi) : "l"(ACC));
    return lo + hi;
}

// streaming uint2 load (evict-first both levels): for dst rows + records
__device__ __forceinline__ uint2 ldcs_u2(const uint2* p)
{
    uint2 v;
    asm("ld.global.cs.v2.u32 {%0,%1}, [%2];" : "=r"(v.x), "=r"(v.y) : "l"(p));
    return v;
}

// ---------------- D: bucketed gather + dot + sigmoid ----------------
__global__ __launch_bounds__(256)
void edge_dot_sigmoid_kernel(float* __restrict__ out)
{
    int bucket = blockIdx.x / BPB;
    int sub    = blockIdx.x % BPB;
    int wid    = threadIdx.x >> 5;
    int lane   = threadIdx.x & 31;

    int start = g_start[bucket];
    int end   = g_start[bucket + 1];

    // warp-chunks of 8 edges, interleaved across the BPB sibling blocks
    for (int i = start + (sub * 8 + wid) * EPW; i < end; i += BPB * 8 * EPW) {
        int cnt = end - i;
        if (cnt >= EPW) {
            // lanes 0-7 load this chunk's records
            int2 rec = make_int2(0, 0);
            int  ev  = 0;
            if (lane < EPW) {
                uint2 r = ldcs_u2(reinterpret_cast<const uint2*>(g_sd + i) + lane);
                rec = make_int2((int)r.x, (int)r.y);
                ev  = __ldcs(&g_se[i + lane]);
            }
            int s[EPW], d[EPW];
            #pragma unroll
            for (int k = 0; k < EPW; k++) {
                s[k] = __shfl_sync(0xffffffffu, rec.x, k);
                d[k] = __shfl_sync(0xffffffffu, rec.y, k);
            }

            // src: L1-cached (bucket window, heavy reuse); dst: streaming.
            uint2 a[EPW], b[EPW];
            #pragma unroll
            for (int k = 0; k < EPW; k++)
                a[k] = __ldg(reinterpret_cast<const uint2*>(
                           g_xh + (long long)s[k] * HIDDEN) + lane);
            #pragma unroll
            for (int k = 0; k < EPW; k++)
                b[k] = ldcs_u2(reinterpret_cast<const uint2*>(
                           g_xh + (long long)d[k] * HIDDEN + HALF) + lane);

            float v[EPW];
            #pragma unroll
            for (int k = 0; k < EPW; k++)
                v[k] = dot4h(a[k], b[k]);

            // merging butterfly: lane l ends with edge (l & 7)
            float m0[4];
            #pragma unroll
            for (int k = 0; k < 4; k++) {
                float e0 = v[2*k]   + __shfl_xor_sync(0xffffffffu, v[2*k],   1);
                float e1 = v[2*k+1] + __shfl_xor_sync(0xffffffffu, v[2*k+1], 1);
                m0[k] = (lane & 1) ? e1 : e0;
            }
            float m1[2];
            #pragma unroll
            for (int k = 0; k < 2; k++) {
                float e0 = m0[2*k]   + __shfl_xor_sync(0xffffffffu, m0[2*k],   2);
                float e1 = m0[2*k+1] + __shfl_xor_sync(0xffffffffu, m0[2*k+1], 2);
                m1[k] = (lane & 2) ? e1 : e0;
            }
            float e0 = m1[0] + __shfl_xor_sync(0xffffffffu, m1[0], 4);
            float e1 = m1[1] + __shfl_xor_sync(0xffffffffu, m1[1], 4);
            float m2 = (lane & 4) ? e1 : e0;
            m2 += __shfl_xor_sync(0xffffffffu, m2, 8);
            m2 += __shfl_xor_sync(0xffffffffu, m2, 16);

            if (lane < EPW)
                out[ev] = sigmoidf(m2);
        } else {
            // tail chunk: warp-per-edge scalar path
            for (int j = i; j < end; j++) {
                int2 rec = __ldg(&g_sd[j]);     // warp-uniform broadcast
                int  ev  = __ldg(&g_se[j]);
                uint2 ua = __ldg(reinterpret_cast<const uint2*>(
                               g_xh + (long long)rec.x * HIDDEN) + lane);
                uint2 ub = __ldg(reinterpret_cast<const uint2*>(
                               g_xh + (long long)rec.y * HIDDEN + HALF) + lane);
                float dot = dot4h(ua, ub);
                #pragma unroll
                for (int off = 16; off > 0; off >>= 1)
                    dot += __shfl_xor_sync(0xffffffffu, dot, off);
                if (lane == 0)
                    out[ev] = sigmoidf(dot);
            }
        }
    }
}

extern "C" void kernel_launch(void* const* d_in, const int* in_sizes, int n_in,
                              void* d_out, int out_size)
{
    const float* x    = (const float*)d_in[0];
    const int*   eidx = (const int*)d_in[1];
    float*       out  = (float*)d_out;

    int n_x     = in_sizes[0];
    int n_nodes = n_x / HIDDEN;
    int n_edges = in_sizes[1] / 2;
    int nbuck   = (n_nodes + (1 << BSHIFT) - 1) >> BSHIFT;

    zero_kernel<<<1, MAX_BUCK>>>();
    hist_kernel<<<256, 256>>>(eidx, n_edges);
    scan_kernel<<<1, MAX_BUCK>>>();
    scatter_kernel<<<512, 256>>>(eidx, n_edges);

    int n8 = n_x / 8;
    convert_kernel<<<(n8 + 255) / 256, 256>>>(x, n8);

    edge_dot_sigmoid_kernel<<<nbuck * BPB, 256>>>(out);
}

// round 17
// speedup vs baseline: 4.4129x; 4.4129x over previous
#include <cuda_runtime.h>
#include <cuda_fp16.h>

// out[e] = sigmoid( dot( x[src[e], 0:128], x[dst[e], 128:256] ) )
// x: [100000, 256] fp32. edge_label_index: [2, N_EDGES] int32 on device.
//
// Two kernels per launch (R13 structure — measured best):
//  1) convert x (102 MB fp32) -> static __device__ fp16 table (51.2 MB).
//     fp32 reads evict_first, fp16 writes evict_last (~14.3 us, at cap).
//  2) gather: 8 edges/warp, per-lane uint2 (4 halves) per half-row,
//     f32x2 packed dot, merging butterfly. NEW vs R13: index loads use
//     ld.global.cs and output stores st.global.cs so the streaming traffic
//     does not evict the L1-resident x rows (L1 reuse is what pushes the
//     gather past the LTS cap).

#define N_NODES 100000
#define HIDDEN  256
#define HALF    128
#define EPW     8     // edges per warp

__device__ static __half g_xh[(size_t)N_NODES * HIDDEN];   // 51.2 MB scratch

__device__ __forceinline__ float sigmoidf(float v)
{
    return __fdividef(1.0f, 1.0f + __expf(-v));
}

__device__ __forceinline__ unsigned long long pol_evict_first()
{
    unsigned long long p;
    asm("createpolicy.fractional.L2::evict_first.b64 %0, 1.0;" : "=l"(p));
    return p;
}
__device__ __forceinline__ unsigned long long pol_evict_last()
{
    unsigned long long p;
    asm("createpolicy.fractional.L2::evict_last.b64 %0, 1.0;" : "=l"(p));
    return p;
}

// ---------------- kernel 1: fp32 -> fp16 table ----------------
__global__ __launch_bounds__(256)
void convert_kernel(const float* __restrict__ x, int n8)
{
    int i = blockIdx.x * blockDim.x + threadIdx.x;
    if (i >= n8) return;

    unsigned long long pf = pol_evict_first();
    unsigned long long pl = pol_evict_last();

    const float4* src = reinterpret_cast<const float4*>(x) + 2 * i;
    float4 v0, v1;
    asm("ld.global.nc.L2::cache_hint.v4.f32 {%0,%1,%2,%3}, [%4], %5;"
        : "=f"(v0.x), "=f"(v0.y), "=f"(v0.z), "=f"(v0.w) : "l"(src), "l"(pf));
    asm("ld.global.nc.L2::cache_hint.v4.f32 {%0,%1,%2,%3}, [%4], %5;"
        : "=f"(v1.x), "=f"(v1.y), "=f"(v1.z), "=f"(v1.w) : "l"(src + 1), "l"(pf));

    __half2 h0 = __floats2half2_rn(v0.x, v0.y);
    __half2 h1 = __floats2half2_rn(v0.z, v0.w);
    __half2 h2 = __floats2half2_rn(v1.x, v1.y);
    __half2 h3 = __floats2half2_rn(v1.z, v1.w);
    unsigned u0 = *reinterpret_cast<unsigned*>(&h0);
    unsigned u1 = *reinterpret_cast<unsigned*>(&h1);
    unsigned u2 = *reinterpret_cast<unsigned*>(&h2);
    unsigned u3 = *reinterpret_cast<unsigned*>(&h3);

    uint4* dst = reinterpret_cast<uint4*>(g_xh) + i;
    asm volatile("st.global.L2::cache_hint.v4.b32 [%0], {%1,%2,%3,%4}, %5;"
                 :: "l"(dst), "r"(u0), "r"(u1), "r"(u2), "r"(u3), "l"(pl)
                 : "memory");
}

// dot of 4 halves vs 4 halves using packed f32x2 FMA, fp32 accumulation
// (R13-measured best for the gather kernel: regs stay at 32).
__device__ __forceinline__ float dot4h(uint2 ua, uint2 ub)
{
    __half2 a0 = *reinterpret_cast<__half2*>(&ua.x);
    __half2 a1 = *reinterpret_cast<__half2*>(&ua.y);
    __half2 b0 = *reinterpret_cast<__half2*>(&ub.x);
    __half2 b1 = *reinterpret_cast<__half2*>(&ub.y);
    float2 fa0 = __half22float2(a0), fa1 = __half22float2(a1);
    float2 fb0 = __half22float2(b0), fb1 = __half22float2(b1);

    unsigned long long A0, B0, A1, B1, ACC;
    asm("mov.b64 %0, {%1, %2};" : "=l"(A0) : "f"(fa0.x), "f"(fa0.y));
    asm("mov.b64 %0, {%1, %2};" : "=l"(B0) : "f"(fb0.x), "f"(fb0.y));
    asm("mov.b64 %0, {%1, %2};" : "=l"(A1) : "f"(fa1.x), "f"(fa1.y));
    asm("mov.b64 %0, {%1, %2};" : "=l"(B1) : "f"(fb1.x), "f"(fb1.y));
    asm("mul.rn.f32x2 %0, %1, %2;" : "=l"(ACC) : "l"(A0), "l"(B0));
    asm("fma.rn.f32x2 %0, %1, %2, %3;" : "=l"(ACC) : "l"(A1), "l"(B1), "l"(ACC));
    float lo, hi;
    asm("mov.b64 {%0, %1}, %2;" : "=f"(lo), "=f"(hi) : "l"(ACC));
    return lo + hi;
}

// streaming int4 load: bypass L1 residency (indices are read once).
__device__ __forceinline__ int4 ldcs_i4(const int4* p)
{
    int4 v;
    asm("ld.global.cs.v4.s32 {%0,%1,%2,%3}, [%4];"
        : "=r"(v.x), "=r"(v.y), "=r"(v.z), "=r"(v.w) : "l"(p));
    return v;
}

// ---------------- kernel 2: edge gather + dot + sigmoid ----------------
__global__ __launch_bounds__(256)
void edge_dot_sigmoid_kernel(const int* __restrict__ eidx,
                             float* __restrict__ out,
                             int n_edges)
{
    int warp = (blockIdx.x * blockDim.x + threadIdx.x) >> 5;
    int lane = threadIdx.x & 31;
    int base = warp * EPW;
    if (base >= n_edges) return;

    if (base + EPW <= n_edges) {
        // Warp-uniform vector index loads (16B requests, streaming).
        int4 s0 = ldcs_i4(reinterpret_cast<const int4*>(eidx + base));
        int4 s1 = ldcs_i4(reinterpret_cast<const int4*>(eidx + base + 4));
        int4 d0 = ldcs_i4(reinterpret_cast<const int4*>(eidx + n_edges + base));
        int4 d1 = ldcs_i4(reinterpret_cast<const int4*>(eidx + n_edges + base + 4));
        int s[EPW] = {s0.x, s0.y, s0.z, s0.w, s1.x, s1.y, s1.z, s1.w};
        int d[EPW] = {d0.x, d0.y, d0.z, d0.w, d1.x, d1.y, d1.z, d1.w};

        // Issue all 16 LDG.64 gathers before any math (MLP=16 per lane).
        uint2 a[EPW], b[EPW];
        #pragma unroll
        for (int k = 0; k < EPW; k++)
            a[k] = __ldg(reinterpret_cast<const uint2*>(
                       g_xh + (long long)s[k] * HIDDEN) + lane);
        #pragma unroll
        for (int k = 0; k < EPW; k++)
            b[k] = __ldg(reinterpret_cast<const uint2*>(
                       g_xh + (long long)d[k] * HIDDEN + HALF) + lane);

        float v[EPW];
        #pragma unroll
        for (int k = 0; k < EPW; k++)
            v[k] = dot4h(a[k], b[k]);

        // Merging butterfly: 8 -> 4 -> 2 -> 1 arrays, then finish the tree.
        float m0[4];
        #pragma unroll
        for (int k = 0; k < 4; k++) {
            float e0 = v[2*k]   + __shfl_xor_sync(0xffffffffu, v[2*k],   1);
            float e1 = v[2*k+1] + __shfl_xor_sync(0xffffffffu, v[2*k+1], 1);
            m0[k] = (lane & 1) ? e1 : e0;
        }
        float m1[2];
        #pragma unroll
        for (int k = 0; k < 2; k++) {
            float e0 = m0[2*k]   + __shfl_xor_sync(0xffffffffu, m0[2*k],   2);
            float e1 = m0[2*k+1] + __shfl_xor_sync(0xffffffffu, m0[2*k+1], 2);
            m1[k] = (lane & 2) ? e1 : e0;
        }
        float e0 = m1[0] + __shfl_xor_sync(0xffffffffu, m1[0], 4);
        float e1 = m1[1] + __shfl_xor_sync(0xffffffffu, m1[1], 4);
        float m2 = (lane & 4) ? e1 : e0;
        m2 += __shfl_xor_sync(0xffffffffu, m2, 8);
        m2 += __shfl_xor_sync(0xffffffffu, m2, 16);
        // lane l now holds the full dot for edge (l & 7).

        if (lane < EPW)
            __stcs(&out[base + lane], sigmoidf(m2));   // streaming store
    } else {
        // Tail: up to EPW-1 edges, scalar path.
        for (int e = base; e < n_edges; e++) {
            int s = __ldcs(&eidx[e]);
            int d = __ldcs(&eidx[n_edges + e]);
            uint2 ua = __ldg(reinterpret_cast<const uint2*>(
                           g_xh + (long long)s * HIDDEN) + lane);
            uint2 ub = __ldg(reinterpret_cast<const uint2*>(
                           g_xh + (long long)d * HIDDEN + HALF) + lane);
            float dot = dot4h(ua, ub);
            #pragma unroll
            for (int off = 16; off > 0; off >>= 1)
                dot += __shfl_xor_sync(0xffffffffu, dot, off);
            if (lane == 0)
                __stcs(&out[e], sigmoidf(dot));
        }
    }
}

extern "C" void kernel_launch(void* const* d_in, const int* in_sizes, int n_in,
                              void* d_out, int out_size)
{
    const float* x    = (const float*)d_in[0];
    const int*   eidx = (const int*)d_in[1];
    float*       out  = (float*)d_out;

    int n_x     = in_sizes[0];       // 25.6M floats (divisible by 8)
    int n_edges = in_sizes[1] / 2;   // edge_label_index has 2*N_EDGES elements

    // Kernel 1: convert table to fp16 (8 floats per thread).
    int n8 = n_x / 8;
    convert_kernel<<<(n8 + 255) / 256, 256>>>(x, n8);

    // Kernel 2: gather + dot + sigmoid.
    const int threads = 256;                       // 8 warps/block
    int warps_per_block = threads / 32;
    int edges_per_block = warps_per_block * EPW;
    int blocks = (n_edges + edges_per_block - 1) / edges_per_block;
    edge_dot_sigmoid_kernel<<<blocks, threads>>>(eidx, out, n_edges);
}